// round 1
// baseline (speedup 1.0000x reference)
#include <cuda_runtime.h>
#include <cuda_bf16.h>
#include <cstdint>

// Problem-fixed shapes (from reference setup_inputs): E=4096, IN=OUT=256, N_NODES=1024
#define MAX_E 4096
#define NN    1024
#define OUTC  256

// ---------------- device scratch (no allocations allowed) ----------------
__device__ float g_s[MAX_E];          // sign per edge: -1 if directed else +1
__device__ float g_dinv[MAX_E];       // 1/sqrt(deg) or 0
__device__ int   g_cnt_src[NN], g_cnt_dst[NN];
__device__ int   g_cur_src[NN], g_cur_dst[NN];
__device__ int   g_off_src[NN + 1], g_off_dst[NN + 1];
__device__ int   g_lst_src[MAX_E], g_lst_dst[MAX_E];
__device__ float g_h[MAX_E * OUTC];   // h = x @ W^T

// ---------------- K1: detect is_directed layout + signs + zero counters ----
__global__ void k_init(const void* __restrict__ isdir, int E) {
    __shared__ int s_any;
    if (threadIdx.x == 0) s_any = 0;
    __syncthreads();
    const unsigned char* b = (const unsigned char*)isdir;
    int local = 0;
    // If stored as int32 (little-endian 0/1), every byte with i%4!=0 is zero.
    for (int i = threadIdx.x; i < E; i += blockDim.x)
        if ((i & 3) != 0) local |= b[i];
    if (local) atomicOr(&s_any, 1);
    __syncthreads();
    bool byte_layout = (s_any != 0);
    const int* bi = (const int*)isdir;
    for (int e = threadIdx.x; e < E; e += blockDim.x) {
        int d = byte_layout ? (b[e] != 0) : (bi[e] != 0);
        g_s[e] = d ? -1.0f : 1.0f;
    }
    for (int n = threadIdx.x; n < NN; n += blockDim.x) {
        g_cnt_src[n] = 0; g_cnt_dst[n] = 0;
        g_cur_src[n] = 0; g_cur_dst[n] = 0;
    }
}

// ---------------- K2: count incident edges per node ----------------------
__global__ void k_count(const int* __restrict__ ei, int E) {
    int e = blockIdx.x * blockDim.x + threadIdx.x;
    if (e < E) {
        atomicAdd(&g_cnt_src[ei[e]], 1);
        atomicAdd(&g_cnt_dst[ei[E + e]], 1);
    }
}

// ---------------- K3: exclusive scan (NN=1024, one block) ----------------
__global__ void k_scan() {
    __shared__ int sm[NN];
    int t = threadIdx.x;
    // src
    sm[t] = g_cnt_src[t]; __syncthreads();
    for (int off = 1; off < NN; off <<= 1) {
        int v = (t >= off) ? sm[t - off] : 0;
        __syncthreads();
        sm[t] += v;
        __syncthreads();
    }
    g_off_src[t + 1] = sm[t];
    if (t == 0) g_off_src[0] = 0;
    __syncthreads();
    // dst
    sm[t] = g_cnt_dst[t]; __syncthreads();
    for (int off = 1; off < NN; off <<= 1) {
        int v = (t >= off) ? sm[t - off] : 0;
        __syncthreads();
        sm[t] += v;
        __syncthreads();
    }
    g_off_dst[t + 1] = sm[t];
    if (t == 0) g_off_dst[0] = 0;
}

// ---------------- K4: fill CSR lists --------------------------------------
__global__ void k_fill(const int* __restrict__ ei, int E) {
    int e = blockIdx.x * blockDim.x + threadIdx.x;
    if (e < E) {
        int s = ei[e], d = ei[E + e];
        int p = g_off_src[s] + atomicAdd(&g_cur_src[s], 1);
        g_lst_src[p] = e;
        int q = g_off_dst[d] + atomicAdd(&g_cur_dst[d], 1);
        g_lst_dst[q] = e;
    }
}

// ---------------- K5: degree -> dinv (warp per edge) ----------------------
__global__ void k_deg(const int* __restrict__ ei, int E) {
    int warp = (blockIdx.x * blockDim.x + threadIdx.x) >> 5;
    int lane = threadIdx.x & 31;
    if (warp >= E) return;
    int e = warp;
    int se = ei[e], de = ei[E + e];
    float acc = 0.0f;
    #pragma unroll
    for (int pass = 0; pass < 4; pass++) {
        int node = (pass < 2) ? se : de;
        const int* lst; int lo, hi;
        if (pass & 1) { lo = g_off_dst[node]; hi = g_off_dst[node + 1]; lst = g_lst_dst; }
        else          { lo = g_off_src[node]; hi = g_off_src[node + 1]; lst = g_lst_src; }
        for (int j = lo + lane; j < hi; j += 32) {
            int f = lst[j];
            int sf = ei[f], df = ei[E + f];
            int ss = (sf == se), sd = (df == se), ds = (sf == de), dd = (df == de);
            int c = ss + dd - sd - ds;
            int k = ss + sd + ds + dd;      // multiplicity of f across the 4 lists
            acc += fabsf((float)c) / (float)k;
        }
    }
    #pragma unroll
    for (int o = 16; o; o >>= 1) acc += __shfl_down_sync(0xffffffffu, acc, o);
    if (lane == 0) g_dinv[e] = (acc > 0.0f) ? rsqrtf(acc) : 0.0f;
}

// ---------------- K6: GEMM  h[m][n] = sum_k x[m][k] * W[n][k] -------------
#define BM 128
#define BN 64
#define BK 16
#define TM 8
#define TN 4
__global__ __launch_bounds__(256, 2)
void k_gemm(const float* __restrict__ A, const float* __restrict__ B,
            float* __restrict__ C, int M, int N, int K) {
    __shared__ float As[BK][BM + 1];
    __shared__ float Bs[BK][BN + 1];
    int m0 = blockIdx.y * BM;
    int n0 = blockIdx.x * BN;
    int tid = threadIdx.x;
    int tx = tid % 16;          // col group (TN=4 -> 64 cols)
    int ty = tid / 16;          // row group (TM=8 -> 128 rows)

    float acc[TM][TN];
    #pragma unroll
    for (int i = 0; i < TM; i++)
        #pragma unroll
        for (int j = 0; j < TN; j++) acc[i][j] = 0.0f;

    for (int k0 = 0; k0 < K; k0 += BK) {
        // load A tile: BM x BK = 512 float4, 2 per thread
        #pragma unroll
        for (int r = 0; r < 2; r++) {
            int idx = tid + 256 * r;
            int row = idx >> 2;
            int kq  = (idx & 3) << 2;
            float4 v = *(const float4*)&A[(size_t)(m0 + row) * K + k0 + kq];
            As[kq + 0][row] = v.x; As[kq + 1][row] = v.y;
            As[kq + 2][row] = v.z; As[kq + 3][row] = v.w;
        }
        // load B tile: BN x BK = 256 float4, 1 per thread
        {
            int n  = tid >> 2;
            int kq = (tid & 3) << 2;
            float4 v = *(const float4*)&B[(size_t)(n0 + n) * K + k0 + kq];
            Bs[kq + 0][n] = v.x; Bs[kq + 1][n] = v.y;
            Bs[kq + 2][n] = v.z; Bs[kq + 3][n] = v.w;
        }
        __syncthreads();

        #pragma unroll
        for (int k = 0; k < BK; k++) {
            float a[TM], b[TN];
            #pragma unroll
            for (int i = 0; i < TM; i++) a[i] = As[k][ty * TM + i];
            #pragma unroll
            for (int j = 0; j < TN; j++) b[j] = Bs[k][tx * TN + j];
            #pragma unroll
            for (int i = 0; i < TM; i++)
                #pragma unroll
                for (int j = 0; j < TN; j++)
                    acc[i][j] = fmaf(a[i], b[j], acc[i][j]);
        }
        __syncthreads();
    }

    #pragma unroll
    for (int i = 0; i < TM; i++) {
        float4 v = make_float4(acc[i][0], acc[i][1], acc[i][2], acc[i][3]);
        *(float4*)&C[(size_t)(m0 + ty * TM + i) * N + n0 + tx * TN] = v;
    }
}

// ---------------- K7: y = D^-1/2 L D^-1/2 h  (warp per edge) --------------
__global__ __launch_bounds__(256)
void k_y(const int* __restrict__ ei, float* __restrict__ y, int E) {
    int warp = (blockIdx.x * blockDim.x + threadIdx.x) >> 5;
    int lane = threadIdx.x & 31;
    if (warp >= E) return;
    int e = warp;
    int se = ei[e], de = ei[E + e];

    float acc[8];
    #pragma unroll
    for (int i = 0; i < 8; i++) acc[i] = 0.0f;

    #pragma unroll
    for (int pass = 0; pass < 4; pass++) {
        int node = (pass < 2) ? se : de;
        const int* lst; int lo, hi;
        if (pass & 1) { lo = g_off_dst[node]; hi = g_off_dst[node + 1]; lst = g_lst_dst; }
        else          { lo = g_off_src[node]; hi = g_off_src[node + 1]; lst = g_lst_src; }
        for (int j = lo; j < hi; j++) {          // uniform across warp
            int f = lst[j];
            int sf = ei[f], df = ei[E + f];
            int ss = (sf == se), sd = (df == se), ds = (sf == de), dd = (df == de);
            int c = ss + dd - sd - ds;
            int k = ss + sd + ds + dd;
            float w = ((float)c / (float)k) * g_s[f] * g_dinv[f];
            if (w != 0.0f) {
                const float4* hp = (const float4*)&g_h[(size_t)f * OUTC + lane * 8];
                float4 v0 = hp[0], v1 = hp[1];
                acc[0] = fmaf(w, v0.x, acc[0]); acc[1] = fmaf(w, v0.y, acc[1]);
                acc[2] = fmaf(w, v0.z, acc[2]); acc[3] = fmaf(w, v0.w, acc[3]);
                acc[4] = fmaf(w, v1.x, acc[4]); acc[5] = fmaf(w, v1.y, acc[5]);
                acc[6] = fmaf(w, v1.z, acc[6]); acc[7] = fmaf(w, v1.w, acc[7]);
            }
        }
    }
    float sc = g_s[e] * g_dinv[e];
    float4 o0 = make_float4(acc[0] * sc, acc[1] * sc, acc[2] * sc, acc[3] * sc);
    float4 o1 = make_float4(acc[4] * sc, acc[5] * sc, acc[6] * sc, acc[7] * sc);
    float4* op = (float4*)&y[(size_t)e * OUTC + lane * 8];
    op[0] = o0; op[1] = o1;
}

// ---------------- launch ---------------------------------------------------
extern "C" void kernel_launch(void* const* d_in, const int* in_sizes, int n_in,
                              void* d_out, int out_size) {
    const float* x     = (const float*)d_in[0];   // [E, IN]
    const float* W     = (const float*)d_in[1];   // [OUT, IN]
    const int*   ei    = (const int*)d_in[2];     // [2, E]
    const void*  isdir = d_in[3];                 // [E] bool or int32

    int E  = in_sizes[2] / 2;
    int IN = in_sizes[0] / E;
    int OUT = in_sizes[1] / IN;
    float* y = (float*)d_out;

    k_init<<<1, 1024>>>(isdir, E);
    k_count<<<(E + 255) / 256, 256>>>(ei, E);
    k_scan<<<1, NN>>>();
    k_fill<<<(E + 255) / 256, 256>>>(ei, E);
    k_deg<<<(E + 7) / 8, 256>>>(ei, E);

    // h = x @ W^T   (M=E, N=OUT, K=IN)
    dim3 ggrid(OUT / BN, E / BM);
    float* h = nullptr;
    cudaGetSymbolAddress((void**)&h, g_h);
    k_gemm<<<ggrid, 256>>>(x, W, h, E, OUT, IN);

    k_y<<<(E + 7) / 8, 256>>>(ei, y, E);
}